// round 6
// baseline (speedup 1.0000x reference)
#include <cuda_runtime.h>

// Problem: N=8192, D=64, H=256
//   h  = tanh(y @ W1 + t*wt + b1)           [N,H]
//   dy = h @ W2 + b2                        [N,D]
//   div_i = sum_j (1 - h_ij^2) * s_j,  s_j = sum_d W1[d,j]*W2[j,d]
//   out = [dy, -div]  -> [N, 65] float32

#define NN 8192
#define DD 64
#define HH 256
#define MT 32            // rows per CTA
#define NT 256           // threads per CTA
#define PITCH (MT + 2)   // 34: even (8B-aligned f32x2) with tolerable conflicts

typedef unsigned long long u64;

__device__ __forceinline__ u64 pack2(float a, float b) {
    u64 r; asm("mov.b64 %0, {%1, %2};" : "=l"(r) : "f"(a), "f"(b)); return r;
}
__device__ __forceinline__ void unpack2(u64 v, float& a, float& b) {
    asm("mov.b64 {%0, %1}, %2;" : "=f"(a), "=f"(b) : "l"(v));
}
// Blackwell packed fp32 FMA (2x FFMA per instruction)
__device__ __forceinline__ u64 fma2(u64 a, u64 b, u64 c) {
    u64 d; asm("fma.rn.f32x2 %0, %1, %2, %3;" : "=l"(d) : "l"(a), "l"(b), "l"(c)); return d;
}
// accurate-enough tanh: correct saturation at +/-inf via __expf/__fdividef
__device__ __forceinline__ float tanh_fast(float x) {
    float e = __expf(2.0f * x);
    return 1.0f - __fdividef(2.0f, e + 1.0f);
}

__global__ void __launch_bounds__(NT) ode_fused(
    const float* __restrict__ tt, const float* __restrict__ y,
    const float* __restrict__ W1, const float* __restrict__ b1,
    const float* __restrict__ wt, const float* __restrict__ W2,
    const float* __restrict__ b2, float* __restrict__ out)
{
    __shared__ float y_s[DD * PITCH];   // transposed y tile: y_s[k][r]
    __shared__ float h_s[HH * PITCH];   // h tile: h_s[j][r]
    __shared__ float c_s[HH];           // t*wt_j + b1_j
    __shared__ float s_s[HH];           // sum_d W1[d,j]*W2[j,d]
    __shared__ float b2_s[DD];
    __shared__ float divp[8 * MT];      // divergence partials

    const int tid  = threadIdx.x;
    const int row0 = blockIdx.x * MT;

    // ---- per-hidden constants (NT == HH: one j per thread) ----
    {
        const int j = tid;
        const float ts = tt[0];
        float c = fmaf(ts, wt[j], b1[j]);
        float s = 0.f;
        #pragma unroll 8
        for (int d = 0; d < DD; d++)
            s = fmaf(W1[d * HH + j], W2[j * DD + d], s);
        c_s[j] = c;
        s_s[j] = s;
        if (tid < DD) b2_s[tid] = b2[tid];
    }

    // ---- load y tile transposed (coalesced float4 reads) ----
    {
        const float4* y4 = (const float4*)(y + (size_t)row0 * DD);
        for (int i = tid; i < MT * DD / 4; i += NT) {
            float4 v = y4[i];
            int r = i >> 4;            // i*4 / 64
            int k = (i & 15) << 2;
            y_s[(k + 0) * PITCH + r] = v.x;
            y_s[(k + 1) * PITCH + r] = v.y;
            y_s[(k + 2) * PITCH + r] = v.z;
            y_s[(k + 3) * PITCH + r] = v.w;
        }
    }
    __syncthreads();

    // ---- Phase A: h = tanh(y@W1 + c) ----
    // thread tile: 8 rows (4 f32x2 pairs) x 4 hidden units
    {
        const int jg = tid & 63, j0 = jg * 4;
        const int rg = tid >> 6, r0 = rg * 8;
        u64 acc[4][4];
        #pragma unroll
        for (int i = 0; i < 4; i++) {
            float c = c_s[j0 + i];
            u64 cc = pack2(c, c);
            #pragma unroll
            for (int p = 0; p < 4; p++) acc[p][i] = cc;
        }
        #pragma unroll 4
        for (int k = 0; k < DD; k++) {
            float4 w = *(const float4*)&W1[k * HH + j0];   // coalesced, L1/L2-hot
            u64 wp0 = pack2(w.x, w.x), wp1 = pack2(w.y, w.y);
            u64 wp2 = pack2(w.z, w.z), wp3 = pack2(w.w, w.w);
            const float* yk = &y_s[k * PITCH + r0];
            #pragma unroll
            for (int p = 0; p < 4; p++) {
                u64 yv = *(const u64*)&yk[2 * p];          // LDS.64 broadcast
                acc[p][0] = fma2(yv, wp0, acc[p][0]);
                acc[p][1] = fma2(yv, wp1, acc[p][1]);
                acc[p][2] = fma2(yv, wp2, acc[p][2]);
                acc[p][3] = fma2(yv, wp3, acc[p][3]);
            }
        }
        #pragma unroll
        for (int i = 0; i < 4; i++) {
            float* hj = &h_s[(j0 + i) * PITCH + r0];
            #pragma unroll
            for (int p = 0; p < 4; p++) {
                float a, b; unpack2(acc[p][i], a, b);
                *(u64*)&hj[2 * p] = pack2(tanh_fast(a), tanh_fast(b));
            }
        }
    }
    __syncthreads();

    // ---- Phase B: dy = h@W2 + b2 ----
    // thread tile: 4 rows (2 f32x2 pairs) x 2 output dims
    {
        const int dg = tid & 31, d0 = dg * 2;
        const int rg = tid >> 5, r0 = rg * 4;
        u64 acc[2][2];
        {
            u64 v0 = pack2(b2_s[d0],     b2_s[d0]);
            u64 v1 = pack2(b2_s[d0 + 1], b2_s[d0 + 1]);
            acc[0][0] = v0; acc[1][0] = v0;
            acc[0][1] = v1; acc[1][1] = v1;
        }
        #pragma unroll 4
        for (int j = 0; j < HH; j++) {
            float2 w = *(const float2*)&W2[j * DD + d0];   // coalesced LDG.64
            u64 wp0 = pack2(w.x, w.x), wp1 = pack2(w.y, w.y);
            const float* hj = &h_s[j * PITCH + r0];
            u64 h0 = *(const u64*)&hj[0];                   // LDS.64 broadcast
            u64 h1 = *(const u64*)&hj[2];
            acc[0][0] = fma2(h0, wp0, acc[0][0]);
            acc[0][1] = fma2(h0, wp1, acc[0][1]);
            acc[1][0] = fma2(h1, wp0, acc[1][0]);
            acc[1][1] = fma2(h1, wp1, acc[1][1]);
        }
        #pragma unroll
        for (int p = 0; p < 2; p++) {
            float a0, b0, a1, b1v;
            unpack2(acc[p][0], a0, b0);
            unpack2(acc[p][1], a1, b1v);
            int r = r0 + 2 * p;
            size_t base0 = (size_t)(row0 + r) * (DD + 1);
            size_t base1 = (size_t)(row0 + r + 1) * (DD + 1);
            out[base0 + d0] = a0; out[base0 + d0 + 1] = a1;
            out[base1 + d0] = b0; out[base1 + d0 + 1] = b1v;
        }
    }

    // ---- divergence: div_r = sum_j (1 - h_rj^2) * s_j ----
    {
        const int r = tid & 31, q = tid >> 5;   // 8 chunks of 32 hidden units
        float g = 0.f;
        #pragma unroll 8
        for (int jj = 0; jj < 32; jj++) {
            int j = q * 32 + jj;
            float h = h_s[j * PITCH + r];       // conflict-free: (2j + r) % 32 distinct in r
            float s = s_s[j];
            g = fmaf(fmaf(-h, h, 1.0f), s, g);
        }
        divp[q * MT + r] = g;
    }
    __syncthreads();
    if (tid < MT) {
        float g = 0.f;
        #pragma unroll
        for (int q = 0; q < 8; q++) g += divp[q * MT + tid];
        out[(size_t)(row0 + tid) * (DD + 1) + DD] = -g;
    }
}

extern "C" void kernel_launch(void* const* d_in, const int* in_sizes, int n_in,
                              void* d_out, int out_size) {
    const float* tt = (const float*)d_in[0];
    const float* y  = (const float*)d_in[1];
    const float* W1 = (const float*)d_in[2];
    const float* b1 = (const float*)d_in[3];
    const float* wt = (const float*)d_in[4];
    const float* W2 = (const float*)d_in[5];
    const float* b2 = (const float*)d_in[6];
    float* out = (float*)d_out;

    ode_fused<<<NN / MT, NT>>>(tt, y, W1, b1, wt, W2, b2, out);
}

// round 8
// speedup vs baseline: 1.3092x; 1.3092x over previous
#include <cuda_runtime.h>

// N=8192, D=64, H=256
//   h  = tanh(y @ W1 + t*wt + b1)      [N,H]
//   dy = h @ W2 + b2                   [N,D]
//   div_i = sum_j (1-h_ij^2) * s_j,  s_j = sum_d W1[d,j]*W2[j,d]
//   out = [dy, -div]  -> [N, 65] float32

#define NN 8192
#define DD 64
#define HH 256
#define MT 32           // rows per CTA
#define NT 256          // threads per CTA

typedef unsigned long long u64;

__device__ float g_s[HH];   // s_j, computed once by prep kernel

__device__ __forceinline__ u64 pack2(float a, float b) {
    u64 r; asm("mov.b64 %0, {%1, %2};" : "=l"(r) : "f"(a), "f"(b)); return r;
}
__device__ __forceinline__ void unpack2(u64 v, float& a, float& b) {
    asm("mov.b64 {%0, %1}, %2;" : "=f"(a), "=f"(b) : "l"(v));
}
// Blackwell packed fp32 FMA (2 FMAs / instruction)
__device__ __forceinline__ u64 fma2(u64 a, u64 b, u64 c) {
    u64 d; asm("fma.rn.f32x2 %0, %1, %2, %3;" : "=l"(d) : "l"(a), "l"(b), "l"(c)); return d;
}
__device__ __forceinline__ float tanh_fast(float x) {
    float e = __expf(2.0f * x);
    return 1.0f - __fdividef(2.0f, e + 1.0f);
}

// ---------------- prep: s_j = sum_d W1[d,j]*W2[j,d], fully coalesced ----------------
__global__ void __launch_bounds__(128) ode_prep(
    const float* __restrict__ W1, const float* __restrict__ W2)
{
    __shared__ float w2s[32][65];
    __shared__ float red[4][32];
    const int t  = threadIdx.x;
    const int j0 = blockIdx.x * 32;

    // stage W2 rows [j0, j0+32) x 64 into smem (coalesced float4)
    const float4* src = (const float4*)(W2 + (size_t)j0 * DD);
    for (int i = t; i < 512; i += 128) {
        float4 v = src[i];
        int jl = i >> 4, d0 = (i & 15) << 2;
        w2s[jl][d0 + 0] = v.x; w2s[jl][d0 + 1] = v.y;
        w2s[jl][d0 + 2] = v.z; w2s[jl][d0 + 3] = v.w;
    }
    __syncthreads();

    const int jl = t & 31, dq = t >> 5;   // 4 d-quarters of 16
    float p = 0.f;
    #pragma unroll
    for (int i = 0; i < 16; i++) {
        int d = dq * 16 + i;
        p = fmaf(W1[d * HH + j0 + jl], w2s[jl][d], p);   // W1 coalesced across jl
    }
    red[dq][jl] = p;
    __syncthreads();
    if (t < 32)
        g_s[j0 + t] = red[0][t] + red[1][t] + red[2][t] + red[3][t];
}

// ---------------- main ----------------
__global__ void __launch_bounds__(NT) ode_main(
    const float* __restrict__ tt, const float* __restrict__ y,
    const float* __restrict__ W1, const float* __restrict__ b1,
    const float* __restrict__ wt, const float* __restrict__ W2,
    const float* __restrict__ b2, float* __restrict__ out)
{
    __shared__ __align__(16) float y_s[MT][65];      // pitch 65: column reads conflict-free
    __shared__ __align__(16) float h_s[HH * MT];     // [j][r], pitch 32
    __shared__ __align__(16) float c_s[HH];
    __shared__ __align__(16) float s_s[HH];
    __shared__ float b2_s[DD];
    __shared__ float divp[8][MT];

    const int tid  = threadIdx.x;
    const int row0 = blockIdx.x * MT;

    // per-hidden constants (all coalesced: 1 wf each)
    c_s[tid] = fmaf(tt[0], wt[tid], b1[tid]);
    s_s[tid] = g_s[tid];
    if (tid < DD) b2_s[tid] = b2[tid];

    // y tile (coalesced float4 LDG, scalar scatter into pitch-65 rows)
    {
        const float4* y4 = (const float4*)(y + (size_t)row0 * DD);
        #pragma unroll
        for (int i = tid; i < MT * DD / 4; i += NT) {
            float4 v = y4[i];
            int r = i >> 4, k0 = (i & 15) << 2;
            y_s[r][k0 + 0] = v.x; y_s[r][k0 + 1] = v.y;
            y_s[r][k0 + 2] = v.z; y_s[r][k0 + 3] = v.w;
        }
    }
    __syncthreads();

    const int rg = tid & 7,  r0 = rg * 4;   // 4 rows per thread

    // ---- Phase A: h = tanh(y@W1 + c). 4 rows x 8 j per thread, f32x2 pairs over j.
    {
        const int jg = tid >> 3, j0 = jg * 8;
        u64 acc[4][4];
        const u64* cp = (const u64*)&c_s[j0];
        #pragma unroll
        for (int p = 0; p < 4; p++) {
            u64 c = cp[p];
            acc[0][p] = c; acc[1][p] = c; acc[2][p] = c; acc[3][p] = c;
        }
        #pragma unroll 4
        for (int k = 0; k < DD; k++) {
            // W1 j-pairs arrive pre-packed: zero packing movs; 1 wf per load per warp
            ulonglong2 wv0 = *(const ulonglong2*)&W1[k * HH + j0];
            ulonglong2 wv1 = *(const ulonglong2*)&W1[k * HH + j0 + 4];
            u64 yp[4];
            #pragma unroll
            for (int r = 0; r < 4; r++) {
                float yv = y_s[r0 + r][k];      // conflict-free scalar LDS
                yp[r] = pack2(yv, yv);
            }
            #pragma unroll
            for (int r = 0; r < 4; r++) {
                acc[r][0] = fma2(yp[r], wv0.x, acc[r][0]);
                acc[r][1] = fma2(yp[r], wv0.y, acc[r][1]);
                acc[r][2] = fma2(yp[r], wv1.x, acc[r][2]);
                acc[r][3] = fma2(yp[r], wv1.y, acc[r][3]);
            }
        }
        // tanh + transpose j-pairs -> row-packed [j][r] columns (aligned STS.128)
        #pragma unroll
        for (int p = 0; p < 4; p++) {
            float a[4], b[4];
            #pragma unroll
            for (int r = 0; r < 4; r++) unpack2(acc[r][p], a[r], b[r]);
            ulonglong2 colA, colB;
            colA.x = pack2(tanh_fast(a[0]), tanh_fast(a[1]));
            colA.y = pack2(tanh_fast(a[2]), tanh_fast(a[3]));
            colB.x = pack2(tanh_fast(b[0]), tanh_fast(b[1]));
            colB.y = pack2(tanh_fast(b[2]), tanh_fast(b[3]));
            int j = j0 + 2 * p;
            *(ulonglong2*)&h_s[(j    ) * MT + r0] = colA;
            *(ulonglong2*)&h_s[(j + 1) * MT + r0] = colB;
        }
    }
    __syncthreads();

    // ---- Phase B: dy = h@W2 + b2. 4 rows x 2 d per thread, pairs over rows.
    {
        const int dg = tid >> 3, d0 = dg * 2;
        u64 accB[2][2];
        {
            u64 v0 = pack2(b2_s[d0],     b2_s[d0]);
            u64 v1 = pack2(b2_s[d0 + 1], b2_s[d0 + 1]);
            accB[0][0] = v0; accB[1][0] = v0;
            accB[0][1] = v1; accB[1][1] = v1;
        }
        #pragma unroll 4
        for (int j = 0; j < HH; j++) {
            ulonglong2 hv = *(const ulonglong2*)&h_s[j * MT + r0]; // 1 wf, no movs
            float2 w = *(const float2*)&W2[j * DD + d0];           // 1 wf per warp
            u64 wp0 = pack2(w.x, w.x), wp1 = pack2(w.y, w.y);
            accB[0][0] = fma2(hv.x, wp0, accB[0][0]);
            accB[0][1] = fma2(hv.x, wp1, accB[0][1]);
            accB[1][0] = fma2(hv.y, wp0, accB[1][0]);
            accB[1][1] = fma2(hv.y, wp1, accB[1][1]);
        }
        #pragma unroll
        for (int p = 0; p < 2; p++) {
            float a0, b0, a1, b1v;
            unpack2(accB[p][0], a0, b0);    // (row r, row r+1) at d0
            unpack2(accB[p][1], a1, b1v);   // (row r, row r+1) at d0+1
            int r = r0 + 2 * p;
            size_t base0 = (size_t)(row0 + r) * (DD + 1);
            size_t base1 = base0 + (DD + 1);
            out[base0 + d0] = a0; out[base0 + d0 + 1] = a1;
            out[base1 + d0] = b0; out[base1 + d0 + 1] = b1v;
        }
    }

    // ---- divergence: div_r = sum_j (1 - h_rj^2) * s_j (h_s reads conflict-free)
    {
        const int r = tid & 31, q = tid >> 5;   // 8 chunks of 32 hidden units
        float g = 0.f;
        #pragma unroll 8
        for (int jj = 0; jj < 32; jj++) {
            int j = q * 32 + jj;
            float h = h_s[j * MT + r];
            g = fmaf(fmaf(-h, h, 1.0f), s_s[j], g);
        }
        divp[q][r] = g;
    }
    __syncthreads();
    if (tid < MT) {
        float g = 0.f;
        #pragma unroll
        for (int q = 0; q < 8; q++) g += divp[q][tid];
        out[(size_t)(row0 + tid) * (DD + 1) + DD] = -g;
    }
}

extern "C" void kernel_launch(void* const* d_in, const int* in_sizes, int n_in,
                              void* d_out, int out_size) {
    const float* tt = (const float*)d_in[0];
    const float* y  = (const float*)d_in[1];
    const float* W1 = (const float*)d_in[2];
    const float* b1 = (const float*)d_in[3];
    const float* wt = (const float*)d_in[4];
    const float* W2 = (const float*)d_in[5];
    const float* b2 = (const float*)d_in[6];
    float* out = (float*)d_out;

    ode_prep<<<HH / 32, 128>>>(W1, W2);
    ode_main<<<NN / MT, NT>>>(tt, y, W1, b1, wt, W2, b2, out);
}

// round 12
// speedup vs baseline: 1.5858x; 1.2112x over previous
#include <cuda_runtime.h>

// N=8192, D=64, H=256
//   h  = tanh(y @ W1 + t*wt + b1)      [N,H]
//   dy = h @ W2 + b2                   [N,D]
//   div_i = sum_j (1-h_ij^2) * s_j,  s_j = sum_d W1[d,j]*W2[j,d]
//   out = [dy, -div]  -> [N, 65] float32

#define NN 8192
#define DD 64
#define HH 256
#define MT 64           // rows per CTA
#define NT 512          // threads per CTA
#define YP 68           // y^T pitch (16B-aligned rows, 2-way store conflicts only)

typedef unsigned long long u64;

__device__ float g_s[HH];   // s_j from prep kernel

__device__ __forceinline__ u64 pack2(float a, float b) {
    u64 r; asm("mov.b64 %0, {%1, %2};" : "=l"(r) : "f"(a), "f"(b)); return r;
}
__device__ __forceinline__ void unpack2(u64 v, float& a, float& b) {
    asm("mov.b64 {%0, %1}, %2;" : "=f"(a), "=f"(b) : "l"(v));
}
// Blackwell packed fp32 FMA (2 FMAs / instruction)
__device__ __forceinline__ u64 fma2(u64 a, u64 b, u64 c) {
    u64 d; asm("fma.rn.f32x2 %0, %1, %2, %3;" : "=l"(d) : "l"(a), "l"(b), "l"(c)); return d;
}
__device__ __forceinline__ float tanh_fast(float x) {
    float e = __expf(2.0f * x);
    return 1.0f - __fdividef(2.0f, e + 1.0f);
}

// ---------------- prep: s_j = sum_d W1[d,j]*W2[j,d], fully coalesced ----------------
__global__ void __launch_bounds__(128) ode_prep(
    const float* __restrict__ W1, const float* __restrict__ W2)
{
    __shared__ float w2s[32][65];
    __shared__ float red[4][32];
    const int t  = threadIdx.x;
    const int j0 = blockIdx.x * 32;

    const float4* src = (const float4*)(W2 + (size_t)j0 * DD);
    for (int i = t; i < 512; i += 128) {
        float4 v = src[i];
        int jl = i >> 4, d0 = (i & 15) << 2;
        w2s[jl][d0 + 0] = v.x; w2s[jl][d0 + 1] = v.y;
        w2s[jl][d0 + 2] = v.z; w2s[jl][d0 + 3] = v.w;
    }
    __syncthreads();

    const int jl = t & 31, dq = t >> 5;
    float p = 0.f;
    #pragma unroll
    for (int i = 0; i < 16; i++) {
        int d = dq * 16 + i;
        p = fmaf(W1[d * HH + j0 + jl], w2s[jl][d], p);
    }
    red[dq][jl] = p;
    __syncthreads();
    if (t < 32)
        g_s[j0 + t] = red[0][t] + red[1][t] + red[2][t] + red[3][t];
}

// ---------------- main: all mainloop operands in smem ----------------
// dynamic smem layout (floats):
//   W1_s: 16384   W2_s: 16384   h_s: 16384 ([j][r] pitch 64)
//   y_s : 64*YP   c_s: 256  s_s: 256  b2_s: 64  divp: 512
#define OFF_W1   0
#define OFF_W2   16384
#define OFF_H    32768
#define OFF_Y    49152
#define OFF_C    (OFF_Y + DD * YP)
#define OFF_S    (OFF_C + HH)
#define OFF_B2   (OFF_S + HH)
#define OFF_DIVP (OFF_B2 + 64)
#define SMEM_FLOATS (OFF_DIVP + 8 * MT)

__global__ void __launch_bounds__(NT, 1) ode_main(
    const float* __restrict__ tt, const float* __restrict__ y,
    const float* __restrict__ W1, const float* __restrict__ b1,
    const float* __restrict__ wt, const float* __restrict__ W2,
    const float* __restrict__ b2, float* __restrict__ out)
{
    extern __shared__ __align__(16) float smem[];
    float* W1_s = smem + OFF_W1;
    float* W2_s = smem + OFF_W2;
    float* h_s  = smem + OFF_H;
    float* y_s  = smem + OFF_Y;
    float* c_s  = smem + OFF_C;
    float* s_s  = smem + OFF_S;
    float* b2_s = smem + OFF_B2;
    float* divp = smem + OFF_DIVP;

    const int tid  = threadIdx.x;
    const int row0 = blockIdx.x * MT;

    // ---- stage weights (coalesced float4, high MLP, once per CTA) ----
    {
        const float4* w1g = (const float4*)W1;
        const float4* w2g = (const float4*)W2;
        float4* w1s = (float4*)W1_s;
        float4* w2s = (float4*)W2_s;
        #pragma unroll
        for (int i = tid; i < 4096; i += NT) w1s[i] = w1g[i];
        #pragma unroll
        for (int i = tid; i < 4096; i += NT) w2s[i] = w2g[i];
    }
    // ---- constants ----
    if (tid < HH) {
        c_s[tid] = fmaf(tt[0], wt[tid], b1[tid]);
        s_s[tid] = g_s[tid];
    }
    if (tid < DD) b2_s[tid] = b2[tid];

    // ---- y tile transposed: y_s[k][r], pitch YP ----
    {
        const float4* y4 = (const float4*)(y + (size_t)row0 * DD);
        #pragma unroll
        for (int i = tid; i < MT * DD / 4; i += NT) {
            float4 v = y4[i];
            int r = i >> 4, k0 = (i & 15) << 2;
            y_s[(k0 + 0) * YP + r] = v.x;
            y_s[(k0 + 1) * YP + r] = v.y;
            y_s[(k0 + 2) * YP + r] = v.z;
            y_s[(k0 + 3) * YP + r] = v.w;
        }
    }
    __syncthreads();

    const int rg = tid & 15, r0 = rg * 4;     // 4 rows per thread (both phases)

    // ---- Phase A: h = tanh(y@W1 + c). 4 rows x 8 j, f32x2 pairs over rows.
    {
        const int jg = tid >> 4, j0 = jg * 8; // 32 j-groups x 8 j = 256
        u64 acc[8][2];
        #pragma unroll
        for (int jj = 0; jj < 8; jj++) {
            float c = c_s[j0 + jj];
            u64 cc = pack2(c, c);
            acc[jj][0] = cc; acc[jj][1] = cc;
        }
        #pragma unroll 4
        for (int k = 0; k < DD; k++) {
            ulonglong2 yv = *(const ulonglong2*)&y_s[k * YP + r0];   // rows r0..r0+3
            float4 wa = *(const float4*)&W1_s[k * HH + j0];
            float4 wb = *(const float4*)&W1_s[k * HH + j0 + 4];
            u64 w0 = pack2(wa.x, wa.x), w1v = pack2(wa.y, wa.y);
            u64 w2v = pack2(wa.z, wa.z), w3 = pack2(wa.w, wa.w);
            u64 w4 = pack2(wb.x, wb.x), w5 = pack2(wb.y, wb.y);
            u64 w6 = pack2(wb.z, wb.z), w7 = pack2(wb.w, wb.w);
            acc[0][0] = fma2(yv.x, w0, acc[0][0]); acc[0][1] = fma2(yv.y, w0, acc[0][1]);
            acc[1][0] = fma2(yv.x, w1v, acc[1][0]); acc[1][1] = fma2(yv.y, w1v, acc[1][1]);
            acc[2][0] = fma2(yv.x, w2v, acc[2][0]); acc[2][1] = fma2(yv.y, w2v, acc[2][1]);
            acc[3][0] = fma2(yv.x, w3, acc[3][0]); acc[3][1] = fma2(yv.y, w3, acc[3][1]);
            acc[4][0] = fma2(yv.x, w4, acc[4][0]); acc[4][1] = fma2(yv.y, w4, acc[4][1]);
            acc[5][0] = fma2(yv.x, w5, acc[5][0]); acc[5][1] = fma2(yv.y, w5, acc[5][1]);
            acc[6][0] = fma2(yv.x, w6, acc[6][0]); acc[6][1] = fma2(yv.y, w6, acc[6][1]);
            acc[7][0] = fma2(yv.x, w7, acc[7][0]); acc[7][1] = fma2(yv.y, w7, acc[7][1]);
        }
        // tanh epilogue: layout already pairs-over-rows -> direct STS.128 to h_s[j][r]
        #pragma unroll
        for (int jj = 0; jj < 8; jj++) {
            float a0, a1, a2, a3;
            unpack2(acc[jj][0], a0, a1);
            unpack2(acc[jj][1], a2, a3);
            ulonglong2 o;
            o.x = pack2(tanh_fast(a0), tanh_fast(a1));
            o.y = pack2(tanh_fast(a2), tanh_fast(a3));
            *(ulonglong2*)&h_s[(j0 + jj) * MT + r0] = o;
        }
    }
    __syncthreads();

    // ---- Phase B: dy = h@W2 + b2. 4 rows x 2 d, pairs over rows, all-smem.
    {
        const int dg = tid >> 4, d0 = dg * 2; // 32 d-groups x 2 = 64
        u64 aB[2][2];
        {
            u64 v0 = pack2(b2_s[d0],     b2_s[d0]);
            u64 v1 = pack2(b2_s[d0 + 1], b2_s[d0 + 1]);
            aB[0][0] = v0; aB[1][0] = v0;
            aB[0][1] = v1; aB[1][1] = v1;
        }
        #pragma unroll 4
        for (int j = 0; j < HH; j++) {
            ulonglong2 hv = *(const ulonglong2*)&h_s[j * MT + r0];
            float2 w = *(const float2*)&W2_s[j * DD + d0];
            u64 wp0 = pack2(w.x, w.x), wp1 = pack2(w.y, w.y);
            aB[0][0] = fma2(hv.x, wp0, aB[0][0]);
            aB[0][1] = fma2(hv.x, wp1, aB[0][1]);
            aB[1][0] = fma2(hv.y, wp0, aB[1][0]);
            aB[1][1] = fma2(hv.y, wp1, aB[1][1]);
        }
        #pragma unroll
        for (int p = 0; p < 2; p++) {
            float a0, b0, a1, b1v;
            unpack2(aB[p][0], a0, b0);     // (row r, row r+1) at d0
            unpack2(aB[p][1], a1, b1v);    // (row r, row r+1) at d0+1
            int r = r0 + 2 * p;
            size_t base0 = (size_t)(row0 + r) * (DD + 1);
            size_t base1 = base0 + (DD + 1);
            out[base0 + d0] = a0; out[base0 + d0 + 1] = a1;
            out[base1 + d0] = b0; out[base1 + d0 + 1] = b1v;
        }
    }

    // ---- divergence: div_r = sum_j (1-h_rj^2)*s_j ----
    {
        const int r = tid & 63, q = tid >> 6;  // 8 j-chunks of 32
        float g = 0.f;
        #pragma unroll 8
        for (int jj = 0; jj < 32; jj++) {
            int j = q * 32 + jj;
            float h = h_s[j * MT + r];         // conflict-free (pitch 64)
            g = fmaf(fmaf(-h, h, 1.0f), s_s[j], g);
        }
        divp[q * MT + r] = g;
    }
    __syncthreads();
    if (tid < MT) {
        float g = 0.f;
        #pragma unroll
        for (int q = 0; q < 8; q++) g += divp[q * MT + tid];
        out[(size_t)(row0 + tid) * (DD + 1) + DD] = -g;
    }
}

extern "C" void kernel_launch(void* const* d_in, const int* in_sizes, int n_in,
                              void* d_out, int out_size) {
    const float* tt = (const float*)d_in[0];
    const float* y  = (const float*)d_in[1];
    const float* W1 = (const float*)d_in[2];
    const float* b1 = (const float*)d_in[3];
    const float* wt = (const float*)d_in[4];
    const float* W2 = (const float*)d_in[5];
    const float* b2 = (const float*)d_in[6];
    float* out = (float*)d_out;

    const int smem_bytes = SMEM_FLOATS * 4;
    cudaFuncSetAttribute(ode_main, cudaFuncAttributeMaxDynamicSharedMemorySize, smem_bytes);

    ode_prep<<<HH / 32, 128>>>(W1, W2);
    ode_main<<<NN / MT, NT, smem_bytes>>>(tt, y, W1, b1, wt, W2, b2, out);
}

// round 13
// speedup vs baseline: 1.7356x; 1.0945x over previous
#include <cuda_runtime.h>

// N=8192, D=64, H=256
//   h  = tanh(y @ W1 + t*wt + b1)      [N,H]
//   dy = h @ W2 + b2                   [N,D]
//   div_i = sum_j (1-h_ij^2) * s_j,  s_j = sum_d W1[d,j]*W2[j,d]
//   out = [dy, -div]  -> [N, 65] float32

#define NN 8192
#define DD 64
#define HH 256
#define MT 32           // rows per CTA
#define NT 256          // threads per CTA
#define Y2P 18          // y pair-pitch (u64 units): 16 pairs + 2 pad

typedef unsigned long long u64;

__device__ float g_s[HH];   // s_j from prep kernel

__device__ __forceinline__ u64 pack2(float a, float b) {
    u64 r; asm("mov.b64 %0, {%1, %2};" : "=l"(r) : "f"(a), "f"(b)); return r;
}
__device__ __forceinline__ void unpack2(u64 v, float& a, float& b) {
    asm("mov.b64 {%0, %1}, %2;" : "=f"(a), "=f"(b) : "l"(v));
}
__device__ __forceinline__ u64 fma2(u64 a, u64 b, u64 c) {
    u64 d; asm("fma.rn.f32x2 %0, %1, %2, %3;" : "=l"(d) : "l"(a), "l"(b), "l"(c)); return d;
}
__device__ __forceinline__ u64 add2(u64 a, u64 b) {
    u64 d; asm("add.rn.f32x2 %0, %1, %2;" : "=l"(d) : "l"(a), "l"(b)); return d;
}
__device__ __forceinline__ float tanh_fast(float x) {
    float e = __expf(2.0f * x);
    return 1.0f - __fdividef(2.0f, e + 1.0f);
}

// ---------------- prep: s_j = sum_d W1[d,j]*W2[j,d], fully coalesced ----------------
__global__ void __launch_bounds__(128) ode_prep(
    const float* __restrict__ W1, const float* __restrict__ W2)
{
    __shared__ float w2s[32][65];
    __shared__ float red[4][32];
    const int t  = threadIdx.x;
    const int j0 = blockIdx.x * 32;

    const float4* src = (const float4*)(W2 + (size_t)j0 * DD);
    for (int i = t; i < 512; i += 128) {
        float4 v = src[i];
        int jl = i >> 4, d0 = (i & 15) << 2;
        w2s[jl][d0 + 0] = v.x; w2s[jl][d0 + 1] = v.y;
        w2s[jl][d0 + 2] = v.z; w2s[jl][d0 + 3] = v.w;
    }
    __syncthreads();

    const int jl = t & 31, dq = t >> 5;
    float p = 0.f;
    #pragma unroll
    for (int i = 0; i < 16; i++) {
        int d = dq * 16 + i;
        p = fmaf(W1[d * HH + j0 + jl], w2s[jl][d], p);
    }
    red[dq][jl] = p;
    __syncthreads();
    if (t < 32)
        g_s[j0 + t] = red[0][t] + red[1][t] + red[2][t] + red[3][t];
}

// ---------------- main ----------------
__global__ void __launch_bounds__(NT, 2) ode_main(
    const float* __restrict__ tt, const float* __restrict__ y,
    const float* __restrict__ W1, const float* __restrict__ b1,
    const float* __restrict__ wt, const float* __restrict__ W2,
    const float* __restrict__ b2, float* __restrict__ out)
{
    __shared__ __align__(16) float h_s[HH * MT];     // [j][r], pitch 32: 32KB
    __shared__ __align__(16) u64   y2[DD * Y2P];     // row-pairs: y2[k][rp]: 9KB
    __shared__ float c_s[HH];
    __shared__ float s_s[HH];
    __shared__ float b2_s[DD];
    __shared__ float divp[8 * MT];

    const int tid  = threadIdx.x;
    const int row0 = blockIdx.x * MT;

    // constants (coalesced, 1 wf each)
    c_s[tid] = fmaf(tt[0], wt[tid], b1[tid]);
    s_s[tid] = g_s[tid];
    if (tid < DD) b2_s[tid] = b2[tid];

    // ---- stage y as row-pairs: y2[k*Y2P + rp] = (y[2rp][k], y[2rp+1][k]) ----
    {
        const int rp = tid & 15, kq = tid >> 4;      // 16 pairs x 16 k-quads
        const float4* yg = (const float4*)(y + (size_t)row0 * DD);
        float4 va = yg[(2 * rp    ) * 16 + kq];
        float4 vb = yg[(2 * rp + 1) * 16 + kq];
        int kb = kq * 4;
        y2[(kb + 0) * Y2P + rp] = pack2(va.x, vb.x);
        y2[(kb + 1) * Y2P + rp] = pack2(va.y, vb.y);
        y2[(kb + 2) * Y2P + rp] = pack2(va.z, vb.z);
        y2[(kb + 3) * Y2P + rp] = pack2(va.w, vb.w);
    }
    __syncthreads();

    const int rowg = tid & 7;
    const int r0   = rowg * 4;
    const int rp0  = rowg * 2;

    // ---- Phase A: h = tanh(y@W1 + c). 4 rows x 8 j per thread; pairs over rows.
    //      y: 1 conflict-free LDS.128 per k per warp; W1: 2 coalesced L1-hot LDG.128.
    {
        const int jg = tid >> 3, j0 = jg * 8;        // 32 j-groups x 8 j
        u64 acc[8][2];
        #pragma unroll
        for (int jj = 0; jj < 8; jj++) {
            float c = c_s[j0 + jj];
            u64 cc = pack2(c, c);
            acc[jj][0] = cc; acc[jj][1] = cc;
        }
        #pragma unroll 4
        for (int k = 0; k < DD; k++) {
            ulonglong2 yv = *(const ulonglong2*)&y2[k * Y2P + rp0];  // rows r0..r0+3
            float4 wa = __ldg((const float4*)&W1[k * HH + j0]);
            float4 wb = __ldg((const float4*)&W1[k * HH + j0 + 4]);
            u64 w0 = pack2(wa.x, wa.x), w1v = pack2(wa.y, wa.y);
            u64 w2v = pack2(wa.z, wa.z), w3 = pack2(wa.w, wa.w);
            u64 w4 = pack2(wb.x, wb.x), w5 = pack2(wb.y, wb.y);
            u64 w6 = pack2(wb.z, wb.z), w7 = pack2(wb.w, wb.w);
            acc[0][0] = fma2(yv.x, w0, acc[0][0]); acc[0][1] = fma2(yv.y, w0, acc[0][1]);
            acc[1][0] = fma2(yv.x, w1v, acc[1][0]); acc[1][1] = fma2(yv.y, w1v, acc[1][1]);
            acc[2][0] = fma2(yv.x, w2v, acc[2][0]); acc[2][1] = fma2(yv.y, w2v, acc[2][1]);
            acc[3][0] = fma2(yv.x, w3, acc[3][0]); acc[3][1] = fma2(yv.y, w3, acc[3][1]);
            acc[4][0] = fma2(yv.x, w4, acc[4][0]); acc[4][1] = fma2(yv.y, w4, acc[4][1]);
            acc[5][0] = fma2(yv.x, w5, acc[5][0]); acc[5][1] = fma2(yv.y, w5, acc[5][1]);
            acc[6][0] = fma2(yv.x, w6, acc[6][0]); acc[6][1] = fma2(yv.y, w6, acc[6][1]);
            acc[7][0] = fma2(yv.x, w7, acc[7][0]); acc[7][1] = fma2(yv.y, w7, acc[7][1]);
        }
        #pragma unroll
        for (int jj = 0; jj < 8; jj++) {
            float a0, a1, a2, a3;
            unpack2(acc[jj][0], a0, a1);
            unpack2(acc[jj][1], a2, a3);
            ulonglong2 o;
            o.x = pack2(tanh_fast(a0), tanh_fast(a1));
            o.y = pack2(tanh_fast(a2), tanh_fast(a3));
            *(ulonglong2*)&h_s[(j0 + jj) * MT + r0] = o;   // STS.128
        }
    }
    __syncthreads();

    // ---- Phase B: dy = h@W2 + b2, j-split across warp halves.
    //      4 rows x 4 d x 128 j per thread; h: 1 conflict-free LDS.128/j/warp.
    u64 aB[2][4];
    const int dg = (tid >> 3) & 15, d0 = dg * 4;
    const int jh = tid >> 7;                          // warps 0-3: j 0-127; 4-7: 128-255
    {
        if (jh == 0) {
            #pragma unroll
            for (int c = 0; c < 4; c++) {
                float b = b2_s[d0 + c];
                u64 bb = pack2(b, b);
                aB[0][c] = bb; aB[1][c] = bb;
            }
        } else {
            #pragma unroll
            for (int c = 0; c < 4; c++) { aB[0][c] = 0; aB[1][c] = 0; }
        }
        const int jbase = jh * 128;
        #pragma unroll 4
        for (int jj = 0; jj < 128; jj++) {
            int j = jbase + jj;
            ulonglong2 hv = *(const ulonglong2*)&h_s[j * MT + r0];
            float4 w = __ldg((const float4*)&W2[j * DD + d0]);
            u64 w0 = pack2(w.x, w.x), w1v = pack2(w.y, w.y);
            u64 w2v = pack2(w.z, w.z), w3 = pack2(w.w, w.w);
            aB[0][0] = fma2(hv.x, w0, aB[0][0]); aB[1][0] = fma2(hv.y, w0, aB[1][0]);
            aB[0][1] = fma2(hv.x, w1v, aB[0][1]); aB[1][1] = fma2(hv.y, w1v, aB[1][1]);
            aB[0][2] = fma2(hv.x, w2v, aB[0][2]); aB[1][2] = fma2(hv.y, w2v, aB[1][2]);
            aB[0][3] = fma2(hv.x, w3, aB[0][3]); aB[1][3] = fma2(hv.y, w3, aB[1][3]);
        }
        // upper half stores partials into psum (aliases dead y2 buffer)
        if (jh == 1) {
            ulonglong2* ps = (ulonglong2*)y2;
            int t1 = tid - 128;
            ps[0 * 128 + t1] = make_ulonglong2(aB[0][0], aB[0][1]);
            ps[1 * 128 + t1] = make_ulonglong2(aB[0][2], aB[0][3]);
            ps[2 * 128 + t1] = make_ulonglong2(aB[1][0], aB[1][1]);
            ps[3 * 128 + t1] = make_ulonglong2(aB[1][2], aB[1][3]);
        }
    }

    // ---- divergence partials (needs only h_s; overlaps with psum drain) ----
    {
        const int r = tid & 31, q = tid >> 5;        // 8 chunks of 32 j
        float g = 0.f;
        #pragma unroll 8
        for (int jj = 0; jj < 32; jj++) {
            int j = q * 32 + jj;
            float h = h_s[j * MT + r];               // bank = r: conflict-free
            g = fmaf(fmaf(-h, h, 1.0f), s_s[j], g);
        }
        divp[q * MT + r] = g;
    }
    __syncthreads();

    // ---- lower half: reduce j-halves, write dy ----
    if (jh == 0) {
        const ulonglong2* ps = (const ulonglong2*)y2;
        ulonglong2 p0 = ps[0 * 128 + tid];
        ulonglong2 p1 = ps[1 * 128 + tid];
        ulonglong2 p2 = ps[2 * 128 + tid];
        ulonglong2 p3 = ps[3 * 128 + tid];
        aB[0][0] = add2(aB[0][0], p0.x); aB[0][1] = add2(aB[0][1], p0.y);
        aB[0][2] = add2(aB[0][2], p1.x); aB[0][3] = add2(aB[0][3], p1.y);
        aB[1][0] = add2(aB[1][0], p2.x); aB[1][1] = add2(aB[1][1], p2.y);
        aB[1][2] = add2(aB[1][2], p3.x); aB[1][3] = add2(aB[1][3], p3.y);
        #pragma unroll
        for (int p = 0; p < 2; p++) {
            size_t base0 = (size_t)(row0 + r0 + 2 * p) * (DD + 1);
            size_t base1 = base0 + (DD + 1);
            #pragma unroll
            for (int c = 0; c < 4; c++) {
                float lo, hi;
                unpack2(aB[p][c], lo, hi);
                out[base0 + d0 + c] = lo;
                out[base1 + d0 + c] = hi;
            }
        }
    }

    // ---- divergence final ----
    if (tid < MT) {
        float g = 0.f;
        #pragma unroll
        for (int q = 0; q < 8; q++) g += divp[q * MT + tid];
        out[(size_t)(row0 + tid) * (DD + 1) + DD] = -g;
    }
}

extern "C" void kernel_launch(void* const* d_in, const int* in_sizes, int n_in,
                              void* d_out, int out_size) {
    const float* tt = (const float*)d_in[0];
    const float* y  = (const float*)d_in[1];
    const float* W1 = (const float*)d_in[2];
    const float* b1 = (const float*)d_in[3];
    const float* wt = (const float*)d_in[4];
    const float* W2 = (const float*)d_in[5];
    const float* b2 = (const float*)d_in[6];
    float* out = (float*)d_out;

    ode_prep<<<HH / 32, 128>>>(W1, W2);
    ode_main<<<NN / MT, NT>>>(tt, y, W1, b1, wt, W2, b2, out);
}